// round 14
// baseline (speedup 1.0000x reference)
#include <cuda_runtime.h>
#include <cstddef>

// ---- problem constants ----
#define HH 384
#define WW 384
#define NPIX (HH*WW)          // 147456
#define BB 4
#define MM 192
#define NT 256
#define NWARP (NT/32)                  // 8
#define T1TILE 16
#define TPX (WW/T1TILE)                // 24 tiles across
#define TPI (TPX*TPX)                  // 576 tiles per image
#define NTILE (BB*TPI)                 // 2304 tiles total
#define NBLK1 (NTILE/NWARP)            // 288 (one warp per tile, 8 tiles/block)
#define BLKPI (NBLK1/BB)               // 72 blocks per image
#define NBLK2 ((BB*MM)/NWARP)          // 96 (one warp per (b,j))
#define TOTBLK (NBLK1+NBLK2)           // 384
#define W2R 17                         // term2 fixed window side
#define EPSF 1e-6f
#define MAX_DISTF 543.0580079975699f   // sqrt(384^2+384^2)
#define EPS_OVER_MAX 1.8414263e-9f     // 1e-6 / MAX_DIST
#define CMINR 0.999999f                // lower bound on c = 1/(p^4+eps')
#define BIGF 3.4e38f

// ---- scratch (static device globals; g_sem reset by finalizer) ----
__device__ float    g_t1part[NTILE];
__device__ float    g_ppart [NTILE];
__device__ float    g_jval  [BB*MM];
__device__ unsigned g_sem;

// ---- packed f32x2 helpers ----
__device__ __forceinline__ unsigned long long pk2(float a, float b) {
    unsigned long long r;
    asm("mov.b64 %0, {%1, %2};" : "=l"(r) : "f"(a), "f"(b));
    return r;
}
__device__ __forceinline__ void upk2(float& a, float& b, unsigned long long v) {
    asm("mov.b64 {%0, %1}, %2;" : "=f"(a), "=f"(b) : "l"(v));
}
__device__ __forceinline__ unsigned long long addx2(unsigned long long a, unsigned long long b) {
    unsigned long long r;
    asm("add.rn.f32x2 %0, %1, %2;" : "=l"(r) : "l"(a), "l"(b));
    return r;
}
__device__ __forceinline__ unsigned long long fmax2(unsigned long long a, unsigned long long b,
                                                    unsigned long long c) {
    unsigned long long r;
    asm("fma.rn.f32x2 %0, %1, %2, %3;" : "=l"(r) : "l"(a), "l"(b), "l"(c));
    return r;
}

__global__ __launch_bounds__(NT, 5)
void whd_all(const float* __restrict__ pm,
             const float* __restrict__ gt,
             const float* __restrict__ osz,
             float* __restrict__ out)
{
    __shared__ float2 s_gt[MM];        // (-gx_norm, -gy_norm) scaled, negated
    __shared__ float  s_red[NWARP*2];
    __shared__ float  s_t1[BB];
    __shared__ bool   s_last;

    const int tid  = threadIdx.x;
    const int lane = tid & 31;
    const int wid  = tid >> 5;
    const int bid  = blockIdx.x;

    if (bid < NBLK2) {
        // ==================== term2 role: one warp per (b,j) ====================
        // Maximize m = q*rsqrt(d2) over a clamped 17x17 fully-in-image window:
        // compile-time rows -> 17 independent LDGs. Exact when M*G*CMINR >= 1.
        const int wg = bid * NWARP + wid;          // 0..767
        const int b  = wg / MM;
        const int j  = wg - b * MM;

        const float fy = osz[2*b+0] * (1.0f/(float)HH);
        const float fx = osz[2*b+1] * (1.0f/(float)WW);
        const float grow = gt[((size_t)b*MM + j)*2 + 0];
        const float gcol = gt[((size_t)b*MM + j)*2 + 1];
        const float* pmb = pm + (size_t)b * NPIX;

        const int cx = (int)gcol;
        const int cy = (int)grow;
        const int x0 = min(max(cx - W2R/2, 0), WW - W2R);
        const int y0 = min(max(cy - W2R/2, 0), HH - W2R);

        float mmax = 0.f;
        if (lane < W2R) {
            const int px = x0 + lane;
            const float dxv = ((float)px - gcol) * fx;
            const float dx2 = dxv * dxv;
            const float* rowp = pmb + (size_t)y0 * WW + px;
            float dyv = ((float)y0 - grow) * fy;
#pragma unroll
            for (int yy = 0; yy < W2R; ++yy) {
                float p  = rowp[(size_t)yy * WW];            // independent loads
                float d2 = fmaf(dyv, dyv, dx2);
                dyv += fy;
                float pp = p*p;
                float q  = fmaf(pp, pp, EPS_OVER_MAX);       // p^4 + eps'
                mmax = fmaxf(mmax, q * rsqrtf(d2));
            }
        }
        unsigned u = __reduce_max_sync(0xffffffffu, __float_as_uint(mmax));
        float M = __uint_as_float(u);

        // certify; rare fallback: generic expanding scan
        {
            const float GBIG = 1.0e18f;
            const int x1 = x0 + W2R - 1, y1 = y0 + W2R - 1;
            float gxl = (x0 == 0)    ? GBIG : (gcol - (float)x0 + 1.0f) * fx;
            float gxh = (x1 == WW-1) ? GBIG : ((float)x1 + 1.0f - gcol) * fx;
            float gyl = (y0 == 0)    ? GBIG : (grow - (float)y0 + 1.0f) * fy;
            float gyh = (y1 == HH-1) ? GBIG : ((float)y1 + 1.0f - grow) * fy;
            float G = fminf(fminf(gxl, gxh), fminf(gyl, gyh));
            if (!(M * G * CMINR >= 1.0f)) {
                int r = 16;
                for (;;) {
                    int ex0 = cx - r, ex1 = cx + r, ey0 = cy - r, ey1 = cy + r;
                    const bool clx0 = (ex0 <= 0), clx1 = (ex1 >= WW-1);
                    const bool cly0 = (ey0 <= 0), cly1 = (ey1 >= HH-1);
                    ex0 = max(ex0, 0); ey0 = max(ey0, 0);
                    ex1 = min(ex1, WW-1); ey1 = min(ey1, HH-1);
                    float mm = 0.f;
                    for (int xs = ex0; xs <= ex1; xs += 32) {
                        int px = xs + lane;
                        if (px <= ex1) {
                            float dxv = ((float)px - gcol) * fx;
                            float dx2 = dxv * dxv;
                            const float* rowp = pmb + (size_t)ey0 * WW + px;
                            float dyv = ((float)ey0 - grow) * fy;
#pragma unroll 4
                            for (int y = ey0; y <= ey1; ++y) {
                                float p  = *rowp; rowp += WW;
                                float d2 = fmaf(dyv, dyv, dx2);
                                dyv += fy;
                                float pp = p*p;
                                float q  = fmaf(pp, pp, EPS_OVER_MAX);
                                mm = fmaxf(mm, q * rsqrtf(d2));
                            }
                        }
                    }
                    unsigned uu = __reduce_max_sync(0xffffffffu, __float_as_uint(mm));
                    M = __uint_as_float(uu);
                    if (clx0 && clx1 && cly0 && cly1) break;
                    float egxl = clx0 ? GBIG : (gcol - (float)ex0 + 1.0f) * fx;
                    float egxh = clx1 ? GBIG : ((float)ex1 + 1.0f - gcol) * fx;
                    float egyl = cly0 ? GBIG : (grow - (float)ey0 + 1.0f) * fy;
                    float egyh = cly1 ? GBIG : ((float)ey1 + 1.0f - grow) * fy;
                    float EG = fminf(fminf(egxl, egxh), fminf(egyl, egyh));
                    if (M * EG * CMINR >= 1.0f) break;
                    r <<= 1;
                }
            }
        }
        if (lane == 0)
            g_jval[wg] = fminf(__fdividef(1.0f, M), MAX_DISTF);  // min d*c, clipped
    } else {
        // ============ term1 role: ONE 16x16 TILE PER WARP (8 tiles/block) ============
        const int tb      = bid - NBLK2;           // 0..287
        const int b       = tb / BLKPI;
        const int tile_id = (tb - b * BLKPI) * NWARP + wid;   // 0..575
        const int tile_y  = tile_id / TPX;
        const int tile_x  = tile_id - tile_y * TPX;

        const float* pmb = pm + (size_t)b * NPIX;
        const float* gtb = gt + (size_t)b * MM * 2;

        const int col0 = tile_x * T1TILE;
        const int row0 = tile_y * T1TILE;
        const int rowg = row0 + (lane >> 1);       // 16 rows x 2 half-rows
        const int colt = col0 + (lane & 1) * 8;    // 8 consecutive columns

        // ---- independent loads first ----
        const float4 pva = *reinterpret_cast<const float4*>(pmb + (size_t)rowg*WW + colt);
        const float4 pvb = *reinterpret_cast<const float4*>(pmb + (size_t)rowg*WW + colt + 4);
        const float fy = osz[2*b+0] * (1.0f/(float)HH);
        const float fx = osz[2*b+1] * (1.0f/(float)WW);

        // stage scaled, negated GT into smem (shared by all 8 tiles of this block)
        if (tid < MM/2) {
            float4 gv = reinterpret_cast<const float4*>(gtb)[tid];  // {y0,x0,y1,x1}
            float4 sv;
            sv.x = -gv.y * fx;  sv.y = -gv.x * fy;
            sv.z = -gv.w * fx;  sv.w = -gv.z * fy;
            reinterpret_cast<float4*>(s_gt)[tid] = sv;
        }

        const float yn = (float)rowg * fy;          // shared across this lane's 8 px
        unsigned long long nxp[4];
#pragma unroll
        for (int k = 0; k < 4; ++k)
            nxp[k] = pk2((float)(colt + 2*k)*fx, (float)(colt + 2*k + 1)*fx);

        const float cxn = ((float)col0 + 7.5f) * fx;
        const float cyn = ((float)row0 + 7.5f) * fy;
        const float hx = 7.5f * fx, hy = 7.5f * fy;
        const float Dh = sqrtf(hx*hx + hy*hy);      // tile half-diagonal

        __syncthreads();                            // s_gt ready (only block-level sync)

        // ---- warp-private cull: lane evaluates 6 points ----
        float dc2[6];
        float mn = BIGF;
#pragma unroll
        for (int g = 0; g < 6; ++g) {
            float2 gv = s_gt[g*32 + lane];
            float ax = gv.x + cxn;
            float ay = gv.y + cyn;
            dc2[g] = fmaf(ax, ax, ay*ay);
            mn = fminf(mn, dc2[g]);
        }
        unsigned um = __reduce_min_sync(0xffffffffu, __float_as_uint(mn));
        float Uc = sqrtf(__uint_as_float(um));
        float thr = Uc + 2.0f*Dh + 1e-2f;
        float thr2 = thr * thr;

        // ---- hot loop: ballot + bit-scan over ~6 candidates ----
        unsigned long long dmn[4] = {pk2(BIGF,BIGF), pk2(BIGF,BIGF),
                                     pk2(BIGF,BIGF), pk2(BIGF,BIGF)};
#pragma unroll
        for (int g = 0; g < 6; ++g) {
            unsigned ball = __ballot_sync(0xffffffffu, dc2[g] <= thr2);
            while (ball) {
                int src = __ffs(ball) - 1;
                ball &= ball - 1;
                float2 gv = s_gt[g*32 + src];       // LDS.64 broadcast
                float dy  = yn + gv.y;              // one dy for all 8 px of this lane
                float dyy = dy * dy;
                unsigned long long dyy2 = pk2(dyy, dyy);
                unsigned long long gx2  = pk2(gv.x, gv.x);
#pragma unroll
                for (int k = 0; k < 4; ++k) {
                    unsigned long long dxp = addx2(nxp[k], gx2);
                    unsigned long long d2a = fmax2(dxp, dxp, dyy2);
                    float a, bx, m0, m1;
                    upk2(a, bx, d2a);
                    upk2(m0, m1, dmn[k]);
                    dmn[k] = pk2(fminf(m0, a), fminf(m1, bx));
                }
            }
        }

        // ---- tile partial: warp-reduce, lane0 writes tile slot (no block reduce) ----
        float d2m[8];
#pragma unroll
        for (int k = 0; k < 4; ++k) upk2(d2m[2*k], d2m[2*k+1], dmn[k]);
        float t1 = pva.x*sqrtf(d2m[0]) + pva.y*sqrtf(d2m[1])
                 + pva.z*sqrtf(d2m[2]) + pva.w*sqrtf(d2m[3])
                 + pvb.x*sqrtf(d2m[4]) + pvb.y*sqrtf(d2m[5])
                 + pvb.z*sqrtf(d2m[6]) + pvb.w*sqrtf(d2m[7]);
        float ps = (pva.x + pva.y + pva.z + pva.w)
                 + (pvb.x + pvb.y + pvb.z + pvb.w);
#pragma unroll
        for (int off = 16; off > 0; off >>= 1) {
            t1 += __shfl_down_sync(0xffffffffu, t1, off);
            ps += __shfl_down_sync(0xffffffffu, ps, off);
        }
        if (lane == 0) {
            g_t1part[b*TPI + tile_id] = t1;
            g_ppart [b*TPI + tile_id] = ps;
        }
    }

    // ==================== common tail: last-block finalize ====================
    __threadfence();
    __syncthreads();
    if (tid == 0) s_last = (atomicAdd(&g_sem, 1u) == (unsigned)(TOTBLK - 1));
    __syncthreads();
    if (!s_last) return;

    // term2 total: fixed-order deterministic sum of 768 values
    float acc = 0.f;
#pragma unroll
    for (int t = tid; t < BB*MM; t += NT) acc += g_jval[t];
#pragma unroll
    for (int off = 16; off > 0; off >>= 1)
        acc += __shfl_down_sync(0xffffffffu, acc, off);

    // term1 ratios: warps 0..3, one image each (576 tiles, lane-strided, fixed-order)
    if (wid < BB) {
        float nu = 0.f, de = 0.f;
        for (int c = lane; c < TPI; c += 32) {
            nu += g_t1part[wid*TPI + c];
            de += g_ppart [wid*TPI + c];
        }
#pragma unroll
        for (int off = 16; off > 0; off >>= 1) {
            nu += __shfl_down_sync(0xffffffffu, nu, off);
            de += __shfl_down_sync(0xffffffffu, de, off);
        }
        if (lane == 0) s_t1[wid] = nu / (de + EPSF);
    }
    if (lane == 0) s_red[wid] = acc;
    __syncthreads();

    if (tid == 0) {
        float t2 = 0.f;
#pragma unroll
        for (int w = 0; w < NWARP; ++w) t2 += s_red[w];
        float t1sum = 0.f;
#pragma unroll
        for (int bb = 0; bb < BB; ++bb) t1sum += s_t1[bb];
        out[0] = t1sum * (1.0f/(float)BB) + t2 * (1.0f/(float)(BB*MM));
        g_sem = 0u;                                // reset for next replay
    }
}

extern "C" void kernel_launch(void* const* d_in, const int* in_sizes, int n_in,
                              void* d_out, int out_size)
{
    const float* pm  = nullptr;
    const float* gt  = nullptr;
    const float* osz = nullptr;
    for (int i = 0; i < n_in; ++i) {
        if      (in_sizes[i] == BB*NPIX) pm  = (const float*)d_in[i];
        else if (in_sizes[i] == BB*MM*2) gt  = (const float*)d_in[i];
        else if (in_sizes[i] == BB*2)    osz = (const float*)d_in[i];
    }
    whd_all<<<TOTBLK, NT>>>(pm, gt, osz, (float*)d_out);
    (void)out_size;
}

// round 15
// speedup vs baseline: 1.4899x; 1.4899x over previous
#include <cuda_runtime.h>
#include <cstddef>

// ---- problem constants ----
#define HH 384
#define WW 384
#define NPIX (HH*WW)          // 147456
#define BB 4
#define MM 192
#define NT 128
#define TILE_W 32
#define TILE_H 32
#define TILES_X (WW/TILE_W)            // 12
#define TILES_Y (HH/TILE_H)            // 12
#define NCHUNK (TILES_X*TILES_Y)       // 144
#define NBLK1 (BB*NCHUNK)              // 576
#define NBLK2 ((BB*MM)/4)              // 192 (4 warps/block, 1 warp per (b,j))
#define TOTBLK (NBLK1+NBLK2)           // 768 -> all resident (128 thr, <=8 CTAs/SM)
#define NWARP (NT/32)                  // 4
#define W2R 17                         // term2 fixed window side
#define EPSF 1e-6f
#define MAX_DISTF 543.0580079975699f   // sqrt(384^2+384^2)
#define EPS_OVER_MAX 1.8414263e-9f     // 1e-6 / MAX_DIST
#define CMINR 0.999999f                // lower bound on c = 1/(p^4+eps')
#define BIGF 3.4e38f

// ---- scratch (static device globals; g_sem reset by finalizer) ----
__device__ float    g_t1part[NBLK1];
__device__ float    g_ppart [NBLK1];
__device__ float    g_jval  [BB*MM];
__device__ unsigned g_sem;

// ---- packed f32x2 helpers ----
__device__ __forceinline__ unsigned long long pk2(float a, float b) {
    unsigned long long r;
    asm("mov.b64 %0, {%1, %2};" : "=l"(r) : "f"(a), "f"(b));
    return r;
}
__device__ __forceinline__ void upk2(float& a, float& b, unsigned long long v) {
    asm("mov.b64 {%0, %1}, %2;" : "=f"(a), "=f"(b) : "l"(v));
}
__device__ __forceinline__ unsigned long long addx2(unsigned long long a, unsigned long long b) {
    unsigned long long r;
    asm("add.rn.f32x2 %0, %1, %2;" : "=l"(r) : "l"(a), "l"(b));
    return r;
}
__device__ __forceinline__ unsigned long long fmax2(unsigned long long a, unsigned long long b,
                                                    unsigned long long c) {
    unsigned long long r;
    asm("fma.rn.f32x2 %0, %1, %2, %3;" : "=l"(r) : "l"(a), "l"(b), "l"(c));
    return r;
}

__global__ __launch_bounds__(NT, 8)
void whd_all(const float* __restrict__ pm,
             const float* __restrict__ gt,
             const float* __restrict__ osz,
             float* __restrict__ out)
{
    __shared__ ulonglong2 s_cand[MM];   // {(-gx,-gx), (-gy,-gy)} packed -> LDS.128
    __shared__ float s_red[NWARP*2];
    __shared__ float s_t1[BB];
    __shared__ int   s_n;
    __shared__ bool  s_last;

    const int tid  = threadIdx.x;
    const int lane = tid & 31;
    const int wid  = tid >> 5;
    const int bid  = blockIdx.x;

    if (tid == 0) s_n = 0;

    if (bid < NBLK2) {
        // ==================== term2 role: one warp per (b,j) ====================
        // Maximize m = q*rsqrt(d2), q = p^4+eps', over a clamped 17x17 window
        // fully inside the image: compile-time rows -> 17 independent LDGs/lane.
        // Exact when M*G*CMINR >= 1 (outside pixel value d*c >= G*CMINR).
        const int wg = bid * NWARP + wid;          // 0..767
        const int b  = wg / MM;
        const int j  = wg - b * MM;

        const float fy = osz[2*b+0] * (1.0f/(float)HH);
        const float fx = osz[2*b+1] * (1.0f/(float)WW);
        const float grow = gt[((size_t)b*MM + j)*2 + 0];
        const float gcol = gt[((size_t)b*MM + j)*2 + 1];
        const float* pmb = pm + (size_t)b * NPIX;

        const int cx = (int)gcol;
        const int cy = (int)grow;
        const int x0 = min(max(cx - W2R/2, 0), WW - W2R);
        const int y0 = min(max(cy - W2R/2, 0), HH - W2R);

        float mmax = 0.f;
        if (lane < W2R) {
            const int px = x0 + lane;
            const float dxv = ((float)px - gcol) * fx;
            const float dx2 = dxv * dxv;
            const float* rowp = pmb + (size_t)y0 * WW + px;
            float dyv = ((float)y0 - grow) * fy;
#pragma unroll
            for (int yy = 0; yy < W2R; ++yy) {
                float p  = rowp[(size_t)yy * WW];            // independent loads, MLP~17
                float d2 = fmaf(dyv, dyv, dx2);
                dyv += fy;
                float pp = p*p;
                float q  = fmaf(pp, pp, EPS_OVER_MAX);       // p^4 + eps'
                mmax = fmaxf(mmax, q * rsqrtf(d2));          // d2=0 -> inf (ok)
            }
        }
        unsigned u = __reduce_max_sync(0xffffffffu, __float_as_uint(mmax));
        float M = __uint_as_float(u);

        // certify; rare fallback: generic expanding column-strip scan
        {
            const float GBIG = 1.0e18f;
            const int x1 = x0 + W2R - 1, y1 = y0 + W2R - 1;
            float gxl = (x0 == 0)    ? GBIG : (gcol - (float)x0 + 1.0f) * fx;
            float gxh = (x1 == WW-1) ? GBIG : ((float)x1 + 1.0f - gcol) * fx;
            float gyl = (y0 == 0)    ? GBIG : (grow - (float)y0 + 1.0f) * fy;
            float gyh = (y1 == HH-1) ? GBIG : ((float)y1 + 1.0f - grow) * fy;
            float G = fminf(fminf(gxl, gxh), fminf(gyl, gyh));
            if (!(M * G * CMINR >= 1.0f)) {
                int r = 16;
                for (;;) {
                    int ex0 = cx - r, ex1 = cx + r, ey0 = cy - r, ey1 = cy + r;
                    const bool clx0 = (ex0 <= 0), clx1 = (ex1 >= WW-1);
                    const bool cly0 = (ey0 <= 0), cly1 = (ey1 >= HH-1);
                    ex0 = max(ex0, 0); ey0 = max(ey0, 0);
                    ex1 = min(ex1, WW-1); ey1 = min(ey1, HH-1);
                    float mm = 0.f;
                    for (int xs = ex0; xs <= ex1; xs += 32) {
                        int px = xs + lane;
                        if (px <= ex1) {
                            float dxv = ((float)px - gcol) * fx;
                            float dx2 = dxv * dxv;
                            const float* rowp = pmb + (size_t)ey0 * WW + px;
                            float dyv = ((float)ey0 - grow) * fy;
#pragma unroll 4
                            for (int y = ey0; y <= ey1; ++y) {
                                float p  = *rowp; rowp += WW;
                                float d2 = fmaf(dyv, dyv, dx2);
                                dyv += fy;
                                float pp = p*p;
                                float q  = fmaf(pp, pp, EPS_OVER_MAX);
                                mm = fmaxf(mm, q * rsqrtf(d2));
                            }
                        }
                    }
                    unsigned uu = __reduce_max_sync(0xffffffffu, __float_as_uint(mm));
                    M = __uint_as_float(uu);
                    if (clx0 && clx1 && cly0 && cly1) break;
                    float egxl = clx0 ? GBIG : (gcol - (float)ex0 + 1.0f) * fx;
                    float egxh = clx1 ? GBIG : ((float)ex1 + 1.0f - gcol) * fx;
                    float egyl = cly0 ? GBIG : (grow - (float)ey0 + 1.0f) * fy;
                    float egyh = cly1 ? GBIG : ((float)ey1 + 1.0f - grow) * fy;
                    float EG = fminf(fminf(egxl, egxh), fminf(egyl, egyh));
                    if (M * EG * CMINR >= 1.0f) break;
                    r <<= 1;
                }
            }
        }
        if (lane == 0)
            g_jval[wg] = fminf(__fdividef(1.0f, M), MAX_DISTF);  // min d*c, clipped
    } else {
        // ==================== term1 role: one 32x32 pixel tile ====================
        // (IDENTICAL to the 11.2us R11 kernel: thread <-> 8-column row run,
        //  2x LDG.128, block-level cull into compact smem list, uniform loop.)
        const int tb    = bid - NBLK2;             // 0..575
        const int b     = tb / NCHUNK;
        const int chunk = tb - b * NCHUNK;
        const int tile_x = chunk % TILES_X;
        const int tile_y = chunk / TILES_X;

        const float* pmb = pm + (size_t)b * NPIX;
        const float* gtb = gt + (size_t)b * MM * 2;

        const int col0 = tile_x * TILE_W;
        const int row0 = tile_y * TILE_H;
        const int rowg = row0 + (tid >> 2);        // 32 rows x 4 runs
        const int colt = col0 + (tid & 3) * 8;     // 8 consecutive columns

        // ---- issue pixel loads first ----
        const float4 pva = *reinterpret_cast<const float4*>(pmb + (size_t)rowg*WW + colt);
        const float4 pvb = *reinterpret_cast<const float4*>(pmb + (size_t)rowg*WW + colt + 4);

        // raw GT coords (two per thread); addresses index-only
        float gry0 = gtb[2*tid + 0];
        float grx0 = gtb[2*tid + 1];
        float gry1 = 0.f, grx1 = 0.f;
        if (tid < MM - NT) {                        // tid < 64: second point
            gry1 = gtb[2*(tid + NT) + 0];
            grx1 = gtb[2*(tid + NT) + 1];
        }
        const float fy = osz[2*b+0] * (1.0f/(float)HH);
        const float fx = osz[2*b+1] * (1.0f/(float)WW);

        const float yn = (float)rowg * fy;          // shared across 8 px of this thread
        unsigned long long nxp[4];
#pragma unroll
        for (int k = 0; k < 4; ++k)
            nxp[k] = pk2((float)(colt + 2*k) * fx, (float)(colt + 2*k + 1) * fx);

        // ---- phase 0: exact candidate culling (triangle inequality) ----
        const float cxn = ((float)col0 + 15.5f) * fx;
        const float cyn = ((float)row0 + 15.5f) * fy;
        const float hx = 15.5f * fx, hy = 15.5f * fy;
        const float Dh = sqrtf(hx*hx + hy*hy);      // tile half-diagonal (normalized)

        float gxn0 = grx0 * fx, gyn0 = gry0 * fy;
        float ax0 = gxn0 - cxn, ay0 = gyn0 - cyn;
        float dc0 = sqrtf(fmaf(ax0, ax0, ay0*ay0));
        float dc1 = BIGF, gxn1 = 0.f, gyn1 = 0.f;
        if (tid < MM - NT) {
            gxn1 = grx1 * fx; gyn1 = gry1 * fy;
            float ax1 = gxn1 - cxn, ay1 = gyn1 - cyn;
            dc1 = sqrtf(fmaf(ax1, ax1, ay1*ay1));
        }
        float dcm = fminf(dc0, dc1);
        unsigned wm = __reduce_min_sync(0xffffffffu, __float_as_uint(dcm));
        if (lane == 0) s_red[wid] = __uint_as_float(wm);
        __syncthreads();
        float Uc = fminf(fminf(s_red[0], s_red[1]), fminf(s_red[2], s_red[3]));
        // point can be a tile pixel's argmin only if dc <= Uc + 2*Dh (+ slack)
        float thr = Uc + 2.0f*Dh + 1e-2f;
        if (dc0 <= thr) {
            int slot = atomicAdd(&s_n, 1);
            ulonglong2 v; v.x = pk2(-gxn0, -gxn0); v.y = pk2(-gyn0, -gyn0);
            s_cand[slot] = v;
        }
        if (dc1 <= thr) {
            int slot = atomicAdd(&s_n, 1);
            ulonglong2 v; v.x = pk2(-gxn1, -gxn1); v.y = pk2(-gyn1, -gyn1);
            s_cand[slot] = v;
        }
        __syncthreads();
        const int ncand = s_n;

        // ---- hot loop over candidates only ----
        unsigned long long dmn[4] = {pk2(BIGF,BIGF), pk2(BIGF,BIGF),
                                     pk2(BIGF,BIGF), pk2(BIGF,BIGF)};
#pragma unroll 2
        for (int jj = 0; jj < ncand; ++jj) {
            ulonglong2 g = s_cand[jj];              // single LDS.128 broadcast
            float gys, gysdup; upk2(gys, gysdup, g.y);
            float dy  = yn + gys;                   // shared across 8 columns
            float dyy = dy * dy;
            unsigned long long dyy2 = pk2(dyy, dyy);
#pragma unroll
            for (int k = 0; k < 4; ++k) {
                unsigned long long dxp = addx2(nxp[k], g.x);
                unsigned long long d2a = fmax2(dxp, dxp, dyy2);
                float a, bx, m0, m1;
                upk2(a, bx, d2a);
                upk2(m0, m1, dmn[k]);
                dmn[k] = pk2(fminf(m0, a), fminf(m1, bx));
            }
        }

        // ---- term1 partial: sum p*sqrt(min d2), sum p ----
        float d2m[8];
#pragma unroll
        for (int k = 0; k < 4; ++k) upk2(d2m[2*k], d2m[2*k+1], dmn[k]);
        float t1 = pva.x*sqrtf(d2m[0]) + pva.y*sqrtf(d2m[1])
                 + pva.z*sqrtf(d2m[2]) + pva.w*sqrtf(d2m[3])
                 + pvb.x*sqrtf(d2m[4]) + pvb.y*sqrtf(d2m[5])
                 + pvb.z*sqrtf(d2m[6]) + pvb.w*sqrtf(d2m[7]);
        float ps = (pva.x + pva.y + pva.z + pva.w)
                 + (pvb.x + pvb.y + pvb.z + pvb.w);
#pragma unroll
        for (int off = 16; off > 0; off >>= 1) {
            t1 += __shfl_down_sync(0xffffffffu, t1, off);
            ps += __shfl_down_sync(0xffffffffu, ps, off);
        }
        __syncthreads();   // protect s_red reuse
        if (lane == 0) { s_red[wid] = t1; s_red[NWARP+wid] = ps; }
        __syncthreads();
        if (tid == 0) {
            float a = 0.f, c2 = 0.f;
#pragma unroll
            for (int w = 0; w < NWARP; ++w) { a += s_red[w]; c2 += s_red[NWARP+w]; }
            g_t1part[tb] = a;
            g_ppart [tb] = c2;
        }
    }

    // ==================== common tail: last-block finalize ====================
    __threadfence();
    __syncthreads();
    if (tid == 0) s_last = (atomicAdd(&g_sem, 1u) == (unsigned)(TOTBLK - 1));
    __syncthreads();
    if (!s_last) return;

    // term2 total: fixed-order deterministic sum of 768 values
    float acc = 0.f;
#pragma unroll
    for (int t = tid; t < BB*MM; t += NT) acc += g_jval[t];
#pragma unroll
    for (int off = 16; off > 0; off >>= 1)
        acc += __shfl_down_sync(0xffffffffu, acc, off);

    // term1 ratios: warps 0..3, one image each (fixed-order)
    {
        float nu = 0.f, de = 0.f;
        for (int c = lane; c < NCHUNK; c += 32) {
            nu += g_t1part[wid*NCHUNK + c];
            de += g_ppart [wid*NCHUNK + c];
        }
#pragma unroll
        for (int off = 16; off > 0; off >>= 1) {
            nu += __shfl_down_sync(0xffffffffu, nu, off);
            de += __shfl_down_sync(0xffffffffu, de, off);
        }
        if (lane == 0) s_t1[wid] = nu / (de + EPSF);
    }
    if (lane == 0) s_red[wid] = acc;
    __syncthreads();

    if (tid == 0) {
        float t2 = 0.f;
#pragma unroll
        for (int w = 0; w < NWARP; ++w) t2 += s_red[w];
        float t1sum = 0.f;
#pragma unroll
        for (int bb = 0; bb < BB; ++bb) t1sum += s_t1[bb];
        out[0] = t1sum * (1.0f/(float)BB) + t2 * (1.0f/(float)(BB*MM));
        g_sem = 0u;                                // reset for next replay
    }
}

extern "C" void kernel_launch(void* const* d_in, const int* in_sizes, int n_in,
                              void* d_out, int out_size)
{
    const float* pm  = nullptr;
    const float* gt  = nullptr;
    const float* osz = nullptr;
    for (int i = 0; i < n_in; ++i) {
        if      (in_sizes[i] == BB*NPIX) pm  = (const float*)d_in[i];
        else if (in_sizes[i] == BB*MM*2) gt  = (const float*)d_in[i];
        else if (in_sizes[i] == BB*2)    osz = (const float*)d_in[i];
    }
    whd_all<<<TOTBLK, NT>>>(pm, gt, osz, (float*)d_out);
    (void)out_size;
}

// round 16
// speedup vs baseline: 1.5343x; 1.0299x over previous
#include <cuda_runtime.h>
#include <cstddef>

// ---- problem constants ----
#define HH 384
#define WW 384
#define NPIX (HH*WW)          // 147456
#define BB 4
#define MM 192
#define NT 128
#define TILE_W 32
#define TILE_H 32
#define TILES_X (WW/TILE_W)            // 12
#define TILES_Y (HH/TILE_H)            // 12
#define NCHUNK (TILES_X*TILES_Y)       // 144
#define NBLK1 (BB*NCHUNK)              // 576
#define NBLK2 ((BB*MM)/4)              // 192 (4 warps/block, 1 warp per (b,j))
#define TOTBLK (NBLK1+NBLK2)           // 768 -> all resident (128 thr, <=8 CTAs/SM)
#define NWARP (NT/32)                  // 4
#define W2R 21                         // term2 fixed window side (21x21)
#define EPSF 1e-6f
#define MAX_DISTF 543.0580079975699f   // sqrt(384^2+384^2)
#define EPS_OVER_MAX 1.8414263e-9f     // 1e-6 / MAX_DIST
#define CMINR 0.999999f                // lower bound on c = 1/(p^4+eps')
#define BIGF 3.4e38f

// ---- scratch (static device globals; g_sem reset by finalizer) ----
__device__ float    g_t1part[NBLK1];
__device__ float    g_ppart [NBLK1];
__device__ float    g_jval  [BB*MM];
__device__ unsigned g_sem;

// ---- packed f32x2 helpers ----
__device__ __forceinline__ unsigned long long pk2(float a, float b) {
    unsigned long long r;
    asm("mov.b64 %0, {%1, %2};" : "=l"(r) : "f"(a), "f"(b));
    return r;
}
__device__ __forceinline__ void upk2(float& a, float& b, unsigned long long v) {
    asm("mov.b64 {%0, %1}, %2;" : "=f"(a), "=f"(b) : "l"(v));
}
__device__ __forceinline__ unsigned long long addx2(unsigned long long a, unsigned long long b) {
    unsigned long long r;
    asm("add.rn.f32x2 %0, %1, %2;" : "=l"(r) : "l"(a), "l"(b));
    return r;
}
__device__ __forceinline__ unsigned long long fmax2(unsigned long long a, unsigned long long b,
                                                    unsigned long long c) {
    unsigned long long r;
    asm("fma.rn.f32x2 %0, %1, %2, %3;" : "=l"(r) : "l"(a), "l"(b), "l"(c));
    return r;
}

__global__ __launch_bounds__(NT, 8)
void whd_all(const float* __restrict__ pm,
             const float* __restrict__ gt,
             const float* __restrict__ osz,
             float* __restrict__ out)
{
    __shared__ ulonglong2 s_cand[MM];   // {(-gx,-gx), (-gy,-gy)} packed -> LDS.128
    __shared__ float s_wm [NWARP];      // cull per-warp minima (dedicated buffer)
    __shared__ float s_red[NWARP*2];
    __shared__ float s_t1[BB];
    __shared__ int   s_n;
    __shared__ bool  s_last;

    const int tid  = threadIdx.x;
    const int lane = tid & 31;
    const int wid  = tid >> 5;
    const int bid  = blockIdx.x;

    if (tid == 0) s_n = 0;

    if (bid < NBLK2) {
        // ==================== term2 role: one warp per (b,j) ====================
        // Maximize m = q*rsqrt(d2), q = p^4+eps', over a clamped 21x21 window
        // fully inside the image: compile-time rows -> 21 independent LDGs/lane.
        // Exact when M*G*CMINR >= 1 (outside pixel value d*c >= G*CMINR).
        const int wg = bid * NWARP + wid;          // 0..767
        const int b  = wg / MM;
        const int j  = wg - b * MM;

        const float fy = osz[2*b+0] * (1.0f/(float)HH);
        const float fx = osz[2*b+1] * (1.0f/(float)WW);
        const float grow = gt[((size_t)b*MM + j)*2 + 0];
        const float gcol = gt[((size_t)b*MM + j)*2 + 1];
        const float* pmb = pm + (size_t)b * NPIX;

        const int cx = (int)gcol;
        const int cy = (int)grow;
        const int x0 = min(max(cx - W2R/2, 0), WW - W2R);
        const int y0 = min(max(cy - W2R/2, 0), HH - W2R);

        float mmax = 0.f;
        if (lane < W2R) {
            const int px = x0 + lane;
            const float dxv = ((float)px - gcol) * fx;
            const float dx2 = dxv * dxv;
            const float* rowp = pmb + (size_t)y0 * WW + px;
            float dyv = ((float)y0 - grow) * fy;
#pragma unroll
            for (int yy = 0; yy < W2R; ++yy) {
                float p  = rowp[(size_t)yy * WW];            // independent loads
                float d2 = fmaf(dyv, dyv, dx2);
                dyv += fy;
                float pp = p*p;
                float q  = fmaf(pp, pp, EPS_OVER_MAX);       // p^4 + eps'
                mmax = fmaxf(mmax, q * rsqrtf(d2));          // d2=0 -> inf (ok)
            }
        }
        unsigned u = __reduce_max_sync(0xffffffffu, __float_as_uint(mmax));
        float M = __uint_as_float(u);

        // certify; rare fallback: generic expanding column-strip scan
        {
            const float GBIG = 1.0e18f;
            const int x1 = x0 + W2R - 1, y1 = y0 + W2R - 1;
            float gxl = (x0 == 0)    ? GBIG : (gcol - (float)x0 + 1.0f) * fx;
            float gxh = (x1 == WW-1) ? GBIG : ((float)x1 + 1.0f - gcol) * fx;
            float gyl = (y0 == 0)    ? GBIG : (grow - (float)y0 + 1.0f) * fy;
            float gyh = (y1 == HH-1) ? GBIG : ((float)y1 + 1.0f - grow) * fy;
            float G = fminf(fminf(gxl, gxh), fminf(gyl, gyh));
            if (!(M * G * CMINR >= 1.0f)) {
                int r = 24;                        // start big: one round certifies
                for (;;) {
                    int ex0 = cx - r, ex1 = cx + r, ey0 = cy - r, ey1 = cy + r;
                    const bool clx0 = (ex0 <= 0), clx1 = (ex1 >= WW-1);
                    const bool cly0 = (ey0 <= 0), cly1 = (ey1 >= HH-1);
                    ex0 = max(ex0, 0); ey0 = max(ey0, 0);
                    ex1 = min(ex1, WW-1); ey1 = min(ey1, HH-1);
                    float mm = 0.f;
                    for (int xs = ex0; xs <= ex1; xs += 32) {
                        int px = xs + lane;
                        if (px <= ex1) {
                            float dxv = ((float)px - gcol) * fx;
                            float dx2 = dxv * dxv;
                            const float* rowp = pmb + (size_t)ey0 * WW + px;
                            float dyv = ((float)ey0 - grow) * fy;
#pragma unroll 4
                            for (int y = ey0; y <= ey1; ++y) {
                                float p  = *rowp; rowp += WW;
                                float d2 = fmaf(dyv, dyv, dx2);
                                dyv += fy;
                                float pp = p*p;
                                float q  = fmaf(pp, pp, EPS_OVER_MAX);
                                mm = fmaxf(mm, q * rsqrtf(d2));
                            }
                        }
                    }
                    unsigned uu = __reduce_max_sync(0xffffffffu, __float_as_uint(mm));
                    M = __uint_as_float(uu);
                    if (clx0 && clx1 && cly0 && cly1) break;
                    float egxl = clx0 ? GBIG : (gcol - (float)ex0 + 1.0f) * fx;
                    float egxh = clx1 ? GBIG : ((float)ex1 + 1.0f - gcol) * fx;
                    float egyl = cly0 ? GBIG : (grow - (float)ey0 + 1.0f) * fy;
                    float egyh = cly1 ? GBIG : ((float)ey1 + 1.0f - grow) * fy;
                    float EG = fminf(fminf(egxl, egxh), fminf(egyl, egyh));
                    if (M * EG * CMINR >= 1.0f) break;
                    r <<= 1;
                }
            }
        }
        if (lane == 0)
            g_jval[wg] = fminf(__fdividef(1.0f, M), MAX_DISTF);  // min d*c, clipped
    } else {
        // ==================== term1 role: one 32x32 pixel tile ====================
        const int tb    = bid - NBLK2;             // 0..575
        const int b     = tb / NCHUNK;
        const int chunk = tb - b * NCHUNK;
        const int tile_x = chunk % TILES_X;
        const int tile_y = chunk / TILES_X;

        const float* pmb = pm + (size_t)b * NPIX;
        const float* gtb = gt + (size_t)b * MM * 2;

        const int col0 = tile_x * TILE_W;
        const int row0 = tile_y * TILE_H;
        const int rowg = row0 + (tid >> 2);        // 32 rows x 4 runs
        const int colt = col0 + (tid & 3) * 8;     // 8 consecutive columns

        // ---- issue pixel loads first ----
        const float4 pva = *reinterpret_cast<const float4*>(pmb + (size_t)rowg*WW + colt);
        const float4 pvb = *reinterpret_cast<const float4*>(pmb + (size_t)rowg*WW + colt + 4);

        // raw GT coords (two per thread); addresses index-only
        float gry0 = gtb[2*tid + 0];
        float grx0 = gtb[2*tid + 1];
        float gry1 = 0.f, grx1 = 0.f;
        if (tid < MM - NT) {                        // tid < 64: second point
            gry1 = gtb[2*(tid + NT) + 0];
            grx1 = gtb[2*(tid + NT) + 1];
        }
        const float fy = osz[2*b+0] * (1.0f/(float)HH);
        const float fx = osz[2*b+1] * (1.0f/(float)WW);

        const float yn = (float)rowg * fy;          // shared across 8 px of this thread
        unsigned long long nxp[4];
#pragma unroll
        for (int k = 0; k < 4; ++k)
            nxp[k] = pk2((float)(colt + 2*k) * fx, (float)(colt + 2*k + 1) * fx);

        // ---- phase 0: exact candidate culling (triangle inequality) ----
        const float cxn = ((float)col0 + 15.5f) * fx;
        const float cyn = ((float)row0 + 15.5f) * fy;
        const float hx = 15.5f * fx, hy = 15.5f * fy;
        const float Dh = sqrtf(hx*hx + hy*hy);      // tile half-diagonal (normalized)

        float gxn0 = grx0 * fx, gyn0 = gry0 * fy;
        float ax0 = gxn0 - cxn, ay0 = gyn0 - cyn;
        float dc0 = sqrtf(fmaf(ax0, ax0, ay0*ay0));
        float dc1 = BIGF, gxn1 = 0.f, gyn1 = 0.f;
        if (tid < MM - NT) {
            gxn1 = grx1 * fx; gyn1 = gry1 * fy;
            float ax1 = gxn1 - cxn, ay1 = gyn1 - cyn;
            dc1 = sqrtf(fmaf(ax1, ax1, ay1*ay1));
        }
        float dcm = fminf(dc0, dc1);
        unsigned wm = __reduce_min_sync(0xffffffffu, __float_as_uint(dcm));
        if (lane == 0) s_wm[wid] = __uint_as_float(wm);
        __syncthreads();
        float Uc = fminf(fminf(s_wm[0], s_wm[1]), fminf(s_wm[2], s_wm[3]));
        // point can be a tile pixel's argmin only if dc <= Uc + 2*Dh (+ slack)
        float thr = Uc + 2.0f*Dh + 1e-2f;
        if (dc0 <= thr) {
            int slot = atomicAdd(&s_n, 1);
            ulonglong2 v; v.x = pk2(-gxn0, -gxn0); v.y = pk2(-gyn0, -gyn0);
            s_cand[slot] = v;
        }
        if (dc1 <= thr) {
            int slot = atomicAdd(&s_n, 1);
            ulonglong2 v; v.x = pk2(-gxn1, -gxn1); v.y = pk2(-gyn1, -gyn1);
            s_cand[slot] = v;
        }
        __syncthreads();
        const int ncand = s_n;

        // ---- hot loop over candidates only ----
        unsigned long long dmn[4] = {pk2(BIGF,BIGF), pk2(BIGF,BIGF),
                                     pk2(BIGF,BIGF), pk2(BIGF,BIGF)};
#pragma unroll 2
        for (int jj = 0; jj < ncand; ++jj) {
            ulonglong2 g = s_cand[jj];              // single LDS.128 broadcast
            float gys, gysdup; upk2(gys, gysdup, g.y);
            float dy  = yn + gys;                   // shared across 8 columns
            float dyy = dy * dy;
            unsigned long long dyy2 = pk2(dyy, dyy);
#pragma unroll
            for (int k = 0; k < 4; ++k) {
                unsigned long long dxp = addx2(nxp[k], g.x);
                unsigned long long d2a = fmax2(dxp, dxp, dyy2);
                float a, bx, m0, m1;
                upk2(a, bx, d2a);
                upk2(m0, m1, dmn[k]);
                dmn[k] = pk2(fminf(m0, a), fminf(m1, bx));
            }
        }

        // ---- term1 partial: sum p*sqrt(min d2), sum p ----
        float d2m[8];
#pragma unroll
        for (int k = 0; k < 4; ++k) upk2(d2m[2*k], d2m[2*k+1], dmn[k]);
        float t1 = pva.x*sqrtf(d2m[0]) + pva.y*sqrtf(d2m[1])
                 + pva.z*sqrtf(d2m[2]) + pva.w*sqrtf(d2m[3])
                 + pvb.x*sqrtf(d2m[4]) + pvb.y*sqrtf(d2m[5])
                 + pvb.z*sqrtf(d2m[6]) + pvb.w*sqrtf(d2m[7]);
        float ps = (pva.x + pva.y + pva.z + pva.w)
                 + (pvb.x + pvb.y + pvb.z + pvb.w);
#pragma unroll
        for (int off = 16; off > 0; off >>= 1) {
            t1 += __shfl_down_sync(0xffffffffu, t1, off);
            ps += __shfl_down_sync(0xffffffffu, ps, off);
        }
        if (lane == 0) { s_red[wid] = t1; s_red[NWARP+wid] = ps; }  // dedicated buffer
        __syncthreads();
        if (tid == 0) {
            float a = 0.f, c2 = 0.f;
#pragma unroll
            for (int w = 0; w < NWARP; ++w) { a += s_red[w]; c2 += s_red[NWARP+w]; }
            g_t1part[tb] = a;
            g_ppart [tb] = c2;
        }
    }

    // ==================== common tail: last-block finalize ====================
    __threadfence();
    __syncthreads();
    if (tid == 0) s_last = (atomicAdd(&g_sem, 1u) == (unsigned)(TOTBLK - 1));
    __syncthreads();
    if (!s_last) return;

    // term2 total: fixed-order deterministic sum of 768 values
    float acc = 0.f;
#pragma unroll
    for (int t = tid; t < BB*MM; t += NT) acc += g_jval[t];
#pragma unroll
    for (int off = 16; off > 0; off >>= 1)
        acc += __shfl_down_sync(0xffffffffu, acc, off);

    // term1 ratios: warps 0..3, one image each (fixed-order)
    {
        float nu = 0.f, de = 0.f;
        for (int c = lane; c < NCHUNK; c += 32) {
            nu += g_t1part[wid*NCHUNK + c];
            de += g_ppart [wid*NCHUNK + c];
        }
#pragma unroll
        for (int off = 16; off > 0; off >>= 1) {
            nu += __shfl_down_sync(0xffffffffu, nu, off);
            de += __shfl_down_sync(0xffffffffu, de, off);
        }
        if (lane == 0) s_t1[wid] = nu / (de + EPSF);
    }
    if (lane == 0) s_wm[wid] = acc;
    __syncthreads();

    if (tid == 0) {
        float t2 = 0.f;
#pragma unroll
        for (int w = 0; w < NWARP; ++w) t2 += s_wm[w];
        float t1sum = 0.f;
#pragma unroll
        for (int bb = 0; bb < BB; ++bb) t1sum += s_t1[bb];
        out[0] = t1sum * (1.0f/(float)BB) + t2 * (1.0f/(float)(BB*MM));
        g_sem = 0u;                                // reset for next replay
    }
}

extern "C" void kernel_launch(void* const* d_in, const int* in_sizes, int n_in,
                              void* d_out, int out_size)
{
    const float* pm  = nullptr;
    const float* gt  = nullptr;
    const float* osz = nullptr;
    for (int i = 0; i < n_in; ++i) {
        if      (in_sizes[i] == BB*NPIX) pm  = (const float*)d_in[i];
        else if (in_sizes[i] == BB*MM*2) gt  = (const float*)d_in[i];
        else if (in_sizes[i] == BB*2)    osz = (const float*)d_in[i];
    }
    whd_all<<<TOTBLK, NT>>>(pm, gt, osz, (float*)d_out);
    (void)out_size;
}

// round 17
// speedup vs baseline: 1.5435x; 1.0060x over previous
#include <cuda_runtime.h>
#include <cstddef>

// ---- problem constants ----
#define HH 384
#define WW 384
#define NPIX (HH*WW)          // 147456
#define BB 4
#define MM 192
#define NT 128
#define TILE_W 32
#define TILE_H 32
#define TILES_X (WW/TILE_W)            // 12
#define TILES_Y (HH/TILE_H)            // 12
#define NCHUNK (TILES_X*TILES_Y)       // 144
#define NBLK1 (BB*NCHUNK)              // 576
#define NBLK2 ((BB*MM)/4)              // 192 (4 warps/block, 1 warp per (b,j))
#define TOTBLK (NBLK1+NBLK2)           // 768 -> all resident (128 thr, <=8 CTAs/SM)
#define NWARP (NT/32)                  // 4
#define W2R 21                         // term2 fixed window side (21x21)
#define EPSF 1e-6f
#define MAX_DISTF 543.0580079975699f   // sqrt(384^2+384^2)
#define EPS_OVER_MAX 1.8414263e-9f     // 1e-6 / MAX_DIST
#define CMINR 0.999999f                // lower bound on c = 1/(p^4+eps')
#define BIGF 3.4e38f

// ---- scratch (static device globals; g_sem reset by finalizer) ----
__device__ float    g_t1part[NBLK1];
__device__ float    g_ppart [NBLK1];
__device__ float    g_jval  [BB*MM];
__device__ unsigned g_sem;

// ---- packed f32x2 helpers ----
__device__ __forceinline__ unsigned long long pk2(float a, float b) {
    unsigned long long r;
    asm("mov.b64 %0, {%1, %2};" : "=l"(r) : "f"(a), "f"(b));
    return r;
}
__device__ __forceinline__ void upk2(float& a, float& b, unsigned long long v) {
    asm("mov.b64 {%0, %1}, %2;" : "=f"(a), "=f"(b) : "l"(v));
}
__device__ __forceinline__ unsigned long long fmax2(unsigned long long a, unsigned long long b,
                                                    unsigned long long c) {
    unsigned long long r;
    asm("fma.rn.f32x2 %0, %1, %2, %3;" : "=l"(r) : "l"(a), "l"(b), "l"(c));
    return r;
}

__global__ __launch_bounds__(NT, 8)
void whd_all(const float* __restrict__ pm,
             const float* __restrict__ gt,
             const float* __restrict__ osz,
             float* __restrict__ out)
{
    __shared__ ulonglong2 s_cand[MM];   // {(-2gx,-2gx), (-gy, gx^2)} -> LDS.128
    __shared__ float s_wm [NWARP];      // cull per-warp minima (dedicated buffer)
    __shared__ float s_red[NWARP*2];
    __shared__ float s_t1[BB];
    __shared__ int   s_n;
    __shared__ bool  s_last;

    const int tid  = threadIdx.x;
    const int lane = tid & 31;
    const int wid  = tid >> 5;
    const int bid  = blockIdx.x;

    if (tid == 0) s_n = 0;

    if (bid < NBLK2) {
        // ==================== term2 role: one warp per (b,j) ====================
        // (identical to R16 winner) Maximize m = q*rsqrt(d2) over clamped 21x21
        // window; exact when M*G*CMINR >= 1; rare expanding-scan fallback.
        const int wg = bid * NWARP + wid;          // 0..767
        const int b  = wg / MM;
        const int j  = wg - b * MM;

        const float fy = osz[2*b+0] * (1.0f/(float)HH);
        const float fx = osz[2*b+1] * (1.0f/(float)WW);
        const float grow = gt[((size_t)b*MM + j)*2 + 0];
        const float gcol = gt[((size_t)b*MM + j)*2 + 1];
        const float* pmb = pm + (size_t)b * NPIX;

        const int cx = (int)gcol;
        const int cy = (int)grow;
        const int x0 = min(max(cx - W2R/2, 0), WW - W2R);
        const int y0 = min(max(cy - W2R/2, 0), HH - W2R);

        float mmax = 0.f;
        if (lane < W2R) {
            const int px = x0 + lane;
            const float dxv = ((float)px - gcol) * fx;
            const float dx2 = dxv * dxv;
            const float* rowp = pmb + (size_t)y0 * WW + px;
            float dyv = ((float)y0 - grow) * fy;
#pragma unroll
            for (int yy = 0; yy < W2R; ++yy) {
                float p  = rowp[(size_t)yy * WW];            // independent loads
                float d2 = fmaf(dyv, dyv, dx2);
                dyv += fy;
                float pp = p*p;
                float q  = fmaf(pp, pp, EPS_OVER_MAX);       // p^4 + eps'
                mmax = fmaxf(mmax, q * rsqrtf(d2));          // d2=0 -> inf (ok)
            }
        }
        unsigned u = __reduce_max_sync(0xffffffffu, __float_as_uint(mmax));
        float M = __uint_as_float(u);

        {
            const float GBIG = 1.0e18f;
            const int x1 = x0 + W2R - 1, y1 = y0 + W2R - 1;
            float gxl = (x0 == 0)    ? GBIG : (gcol - (float)x0 + 1.0f) * fx;
            float gxh = (x1 == WW-1) ? GBIG : ((float)x1 + 1.0f - gcol) * fx;
            float gyl = (y0 == 0)    ? GBIG : (grow - (float)y0 + 1.0f) * fy;
            float gyh = (y1 == HH-1) ? GBIG : ((float)y1 + 1.0f - grow) * fy;
            float G = fminf(fminf(gxl, gxh), fminf(gyl, gyh));
            if (!(M * G * CMINR >= 1.0f)) {
                int r = 24;
                for (;;) {
                    int ex0 = cx - r, ex1 = cx + r, ey0 = cy - r, ey1 = cy + r;
                    const bool clx0 = (ex0 <= 0), clx1 = (ex1 >= WW-1);
                    const bool cly0 = (ey0 <= 0), cly1 = (ey1 >= HH-1);
                    ex0 = max(ex0, 0); ey0 = max(ey0, 0);
                    ex1 = min(ex1, WW-1); ey1 = min(ey1, HH-1);
                    float mm = 0.f;
                    for (int xs = ex0; xs <= ex1; xs += 32) {
                        int px = xs + lane;
                        if (px <= ex1) {
                            float dxv = ((float)px - gcol) * fx;
                            float dx2 = dxv * dxv;
                            const float* rowp = pmb + (size_t)ey0 * WW + px;
                            float dyv = ((float)ey0 - grow) * fy;
#pragma unroll 4
                            for (int y = ey0; y <= ey1; ++y) {
                                float p  = *rowp; rowp += WW;
                                float d2 = fmaf(dyv, dyv, dx2);
                                dyv += fy;
                                float pp = p*p;
                                float q  = fmaf(pp, pp, EPS_OVER_MAX);
                                mm = fmaxf(mm, q * rsqrtf(d2));
                            }
                        }
                    }
                    unsigned uu = __reduce_max_sync(0xffffffffu, __float_as_uint(mm));
                    M = __uint_as_float(uu);
                    if (clx0 && clx1 && cly0 && cly1) break;
                    float egxl = clx0 ? GBIG : (gcol - (float)ex0 + 1.0f) * fx;
                    float egxh = clx1 ? GBIG : ((float)ex1 + 1.0f - gcol) * fx;
                    float egyl = cly0 ? GBIG : (grow - (float)ey0 + 1.0f) * fy;
                    float egyh = cly1 ? GBIG : ((float)ey1 + 1.0f - grow) * fy;
                    float EG = fminf(fminf(egxl, egxh), fminf(egyl, egyh));
                    if (M * EG * CMINR >= 1.0f) break;
                    r <<= 1;
                }
            }
        }
        if (lane == 0)
            g_jval[wg] = fminf(__fdividef(1.0f, M), MAX_DISTF);  // min d*c, clipped
    } else {
        // ==================== term1 role: one 32x32 pixel tile ====================
        // Hot loop uses expanded quadratic: min_j d2 = x^2 + min_j e_j where
        // e_j = (-2gx)*x + (gx^2 + dy^2): one fma.f32x2 per 2 pixels.
        const int tb    = bid - NBLK2;             // 0..575
        const int b     = tb / NCHUNK;
        const int chunk = tb - b * NCHUNK;
        const int tile_x = chunk % TILES_X;
        const int tile_y = chunk / TILES_X;

        const float* pmb = pm + (size_t)b * NPIX;
        const float* gtb = gt + (size_t)b * MM * 2;

        const int col0 = tile_x * TILE_W;
        const int row0 = tile_y * TILE_H;
        const int rowg = row0 + (tid >> 2);        // 32 rows x 4 runs
        const int colt = col0 + (tid & 3) * 8;     // 8 consecutive columns

        // ---- issue pixel loads first ----
        const float4 pva = *reinterpret_cast<const float4*>(pmb + (size_t)rowg*WW + colt);
        const float4 pvb = *reinterpret_cast<const float4*>(pmb + (size_t)rowg*WW + colt + 4);

        // raw GT coords (two per thread); addresses index-only
        float gry0 = gtb[2*tid + 0];
        float grx0 = gtb[2*tid + 1];
        float gry1 = 0.f, grx1 = 0.f;
        if (tid < MM - NT) {                        // tid < 64: second point
            gry1 = gtb[2*(tid + NT) + 0];
            grx1 = gtb[2*(tid + NT) + 1];
        }
        const float fy = osz[2*b+0] * (1.0f/(float)HH);
        const float fx = osz[2*b+1] * (1.0f/(float)WW);

        const float yn = (float)rowg * fy;          // shared across 8 px of this thread
        float xs_[8];                               // normalized x per column
        unsigned long long nxp[4];
#pragma unroll
        for (int k = 0; k < 4; ++k) {
            xs_[2*k]   = (float)(colt + 2*k)     * fx;
            xs_[2*k+1] = (float)(colt + 2*k + 1) * fx;
            nxp[k] = pk2(xs_[2*k], xs_[2*k+1]);
        }

        // ---- phase 0: exact candidate culling (triangle inequality) ----
        const float cxn = ((float)col0 + 15.5f) * fx;
        const float cyn = ((float)row0 + 15.5f) * fy;
        const float hx = 15.5f * fx, hy = 15.5f * fy;
        const float Dh = sqrtf(hx*hx + hy*hy);      // tile half-diagonal (normalized)

        float gxn0 = grx0 * fx, gyn0 = gry0 * fy;
        float ax0 = gxn0 - cxn, ay0 = gyn0 - cyn;
        float dc0 = sqrtf(fmaf(ax0, ax0, ay0*ay0));
        float dc1 = BIGF, gxn1 = 0.f, gyn1 = 0.f;
        if (tid < MM - NT) {
            gxn1 = grx1 * fx; gyn1 = gry1 * fy;
            float ax1 = gxn1 - cxn, ay1 = gyn1 - cyn;
            dc1 = sqrtf(fmaf(ax1, ax1, ay1*ay1));
        }
        float dcm = fminf(dc0, dc1);
        unsigned wm = __reduce_min_sync(0xffffffffu, __float_as_uint(dcm));
        if (lane == 0) s_wm[wid] = __uint_as_float(wm);
        __syncthreads();
        float Uc = fminf(fminf(s_wm[0], s_wm[1]), fminf(s_wm[2], s_wm[3]));
        float thr = Uc + 2.0f*Dh + 1e-2f;
        if (dc0 <= thr) {
            int slot = atomicAdd(&s_n, 1);
            ulonglong2 v;
            v.x = pk2(-2.0f*gxn0, -2.0f*gxn0);
            v.y = pk2(-gyn0, gxn0*gxn0);
            s_cand[slot] = v;
        }
        if (dc1 <= thr) {
            int slot = atomicAdd(&s_n, 1);
            ulonglong2 v;
            v.x = pk2(-2.0f*gxn1, -2.0f*gxn1);
            v.y = pk2(-gyn1, gxn1*gxn1);
            s_cand[slot] = v;
        }
        __syncthreads();
        const int ncand = s_n;

        // ---- hot loop: accumulate min of e_j = (-2gx)*x + (gx^2 + dy^2) ----
        unsigned long long emn[4] = {pk2(BIGF,BIGF), pk2(BIGF,BIGF),
                                     pk2(BIGF,BIGF), pk2(BIGF,BIGF)};
#pragma unroll 2
        for (int jj = 0; jj < ncand; ++jj) {
            ulonglong2 g = s_cand[jj];              // single LDS.128 broadcast
            float gyneg, gx2s; upk2(gyneg, gx2s, g.y);
            float dy = yn + gyneg;
            float h  = fmaf(dy, dy, gx2s);          // gx^2 + dy^2
            unsigned long long h2 = pk2(h, h);
#pragma unroll
            for (int k = 0; k < 4; ++k) {
                unsigned long long e2 = fmax2(g.x, nxp[k], h2);  // (-2gx)*x + h
                float a, bx, m0, m1;
                upk2(a, bx, e2);
                upk2(m0, m1, emn[k]);
                emn[k] = pk2(fminf(m0, a), fminf(m1, bx));
            }
        }

        // ---- term1 partial: d2 = max(x^2 + e_min, 0); sum p*sqrt(d2), sum p ----
        float em[8];
#pragma unroll
        for (int k = 0; k < 4; ++k) upk2(em[2*k], em[2*k+1], emn[k]);
        float d2m[8];
#pragma unroll
        for (int i = 0; i < 8; ++i)
            d2m[i] = fmaxf(fmaf(xs_[i], xs_[i], em[i]), 0.0f);
        float t1 = pva.x*sqrtf(d2m[0]) + pva.y*sqrtf(d2m[1])
                 + pva.z*sqrtf(d2m[2]) + pva.w*sqrtf(d2m[3])
                 + pvb.x*sqrtf(d2m[4]) + pvb.y*sqrtf(d2m[5])
                 + pvb.z*sqrtf(d2m[6]) + pvb.w*sqrtf(d2m[7]);
        float ps = (pva.x + pva.y + pva.z + pva.w)
                 + (pvb.x + pvb.y + pvb.z + pvb.w);
#pragma unroll
        for (int off = 16; off > 0; off >>= 1) {
            t1 += __shfl_down_sync(0xffffffffu, t1, off);
            ps += __shfl_down_sync(0xffffffffu, ps, off);
        }
        if (lane == 0) { s_red[wid] = t1; s_red[NWARP+wid] = ps; }
        __syncthreads();
        if (tid == 0) {
            float a = 0.f, c2 = 0.f;
#pragma unroll
            for (int w = 0; w < NWARP; ++w) { a += s_red[w]; c2 += s_red[NWARP+w]; }
            g_t1part[tb] = a;
            g_ppart [tb] = c2;
        }
    }

    // ==================== common tail: last-block finalize ====================
    __threadfence();
    __syncthreads();
    if (tid == 0) s_last = (atomicAdd(&g_sem, 1u) == (unsigned)(TOTBLK - 1));
    __syncthreads();
    if (!s_last) return;

    // term2 total: fixed-order deterministic sum of 768 values
    float acc = 0.f;
#pragma unroll
    for (int t = tid; t < BB*MM; t += NT) acc += g_jval[t];
#pragma unroll
    for (int off = 16; off > 0; off >>= 1)
        acc += __shfl_down_sync(0xffffffffu, acc, off);

    // term1 ratios: warps 0..3, one image each (fixed-order)
    {
        float nu = 0.f, de = 0.f;
        for (int c = lane; c < NCHUNK; c += 32) {
            nu += g_t1part[wid*NCHUNK + c];
            de += g_ppart [wid*NCHUNK + c];
        }
#pragma unroll
        for (int off = 16; off > 0; off >>= 1) {
            nu += __shfl_down_sync(0xffffffffu, nu, off);
            de += __shfl_down_sync(0xffffffffu, de, off);
        }
        if (lane == 0) s_t1[wid] = nu / (de + EPSF);
    }
    if (lane == 0) s_wm[wid] = acc;
    __syncthreads();

    if (tid == 0) {
        float t2 = 0.f;
#pragma unroll
        for (int w = 0; w < NWARP; ++w) t2 += s_wm[w];
        float t1sum = 0.f;
#pragma unroll
        for (int bb = 0; bb < BB; ++bb) t1sum += s_t1[bb];
        out[0] = t1sum * (1.0f/(float)BB) + t2 * (1.0f/(float)(BB*MM));
        g_sem = 0u;                                // reset for next replay
    }
}

extern "C" void kernel_launch(void* const* d_in, const int* in_sizes, int n_in,
                              void* d_out, int out_size)
{
    const float* pm  = nullptr;
    const float* gt  = nullptr;
    const float* osz = nullptr;
    for (int i = 0; i < n_in; ++i) {
        if      (in_sizes[i] == BB*NPIX) pm  = (const float*)d_in[i];
        else if (in_sizes[i] == BB*MM*2) gt  = (const float*)d_in[i];
        else if (in_sizes[i] == BB*2)    osz = (const float*)d_in[i];
    }
    whd_all<<<TOTBLK, NT>>>(pm, gt, osz, (float*)d_out);
    (void)out_size;
}